// round 4
// baseline (speedup 1.0000x reference)
#include <cuda_runtime.h>
#include <math.h>

#define Bb 4
#define Nn 20000
#define Cc 256
#define Ss 1024
#define Vv 300
#define NCH 20   // chunks of 1024 covering 20000

// ---- output layout (floats), flattened reference tuple order ----
#define O_OBJ   ((size_t)0)                       // [B,2,N]   160000
#define O_GR    (O_OBJ   + (size_t)Bb*2*Nn)       // [B,N]      80000
#define O_GXYZ  (O_GR    + (size_t)Bb*Nn)         // [B,S,3]    12288
#define O_GIND  (O_GXYZ  + (size_t)Bb*Ss*3)       // [B,S]       4096
#define O_GFEAT (O_GIND  + (size_t)Bb*Ss)         // [B,C,S]  1048576
#define O_FP2   (O_GFEAT + (size_t)Bb*Cc*Ss)      // [B,S]       4096
#define O_VP    (O_FP2   + (size_t)Bb*Ss)         // [B,S,3]    12288
#define O_TVI   (O_VP    + (size_t)Bb*Ss*3)       // [B,S]       4096
#define O_ROT   (O_TVI   + (size_t)Bb*Ss)         // [B,S,3,3]  36864

// ---- packed f32x2 helpers (B300: doubles fp32 FMA throughput) ----
#define FMA_F32X2(d,a,b,c) \
    asm("fma.rn.f32x2 %0, %1, %2, %3;" : "=l"(d) : "l"(a), "l"(b), "l"(c))
#define PACK2(out, lo, hi) \
    asm("mov.b64 %0, {%1, %2};" : "=l"(out) : "f"(lo), "f"(hi))
#define UNPACK2(lo, hi, in) \
    asm("mov.b64 {%0, %1}, %2;" : "=f"(lo), "=f"(hi) : "l"(in))

// ---- scratch (device globals; no allocation allowed) ----
__device__ float g_w1t[Cc*Cc];
__device__ float g_c1t[Cc*Cc];
__device__ float g_cx[Bb][Nn];
__device__ float g_cy[Bb][Nn];
__device__ float g_cz[Bb][Nn];
__device__ int   g_cidx[Bb][Nn];
__device__ int   g_count[Bb];
__device__ int   g_ccnt[Bb][NCH];
__device__ int   g_coff[Bb][NCH];
__device__ int   g_inds[Bb][Ss];
__device__ float g_tn[Vv*3];

// ============================================================
// K0: template views (double math mirroring numpy, then fp32 normalize)
// ============================================================
__global__ void k_templates() {
    int i = blockIdx.x*blockDim.x + threadIdx.x;
    if (i >= Vv) return;
    double phi = (sqrt(5.0) - 1.0) / 2.0;
    double z   = (2.0*(double)i + 1.0)/(double)Vv - 1.0;
    double r2  = 1.0 - z*z; if (r2 < 0.0) r2 = 0.0;
    double r   = sqrt(r2);
    double ang = ((2.0*3.141592653589793)*(double)i)*phi;
    float x = (float)(r*cos(ang));
    float y = (float)(r*sin(ang));
    float zf = (float)z;
    float nrm = sqrtf(__fadd_rn(__fadd_rn(__fmul_rn(x,x),__fmul_rn(y,y)),__fmul_rn(zf,zf)));
    float den = fmaxf(nrm, 1e-8f);
    g_tn[i*3+0] = x/den; g_tn[i*3+1] = y/den; g_tn[i*3+2] = zf/den;
}

// ============================================================
// K0b: transpose both 256x256 weight matrices
// ============================================================
__global__ void k_transpose(const float* __restrict__ w1, const float* __restrict__ c1) {
    int idx = blockIdx.x*blockDim.x + threadIdx.x;
    if (idx < Cc*Cc) {
        int o = idx >> 8, k = idx & 255;
        g_w1t[k*Cc + o] = w1[idx];
        g_c1t[k*Cc + o] = c1[idx];
    }
}

// ============================================================
// K1: fused GEMM1 + BN + ReLU + W2 head (packed f32x2 FMA)
// ============================================================
__global__ void __launch_bounds__(256) k_gemm1(
    const float* __restrict__ feat, const float* __restrict__ b1,
    const float* __restrict__ gg,   const float* __restrict__ gbe,
    const float* __restrict__ gm,   const float* __restrict__ gv,
    const float* __restrict__ w2,   const float* __restrict__ b2,
    float* __restrict__ out)
{
    __shared__ float SM[32*256];
    __shared__ float Fs[32][64];
    int b  = blockIdx.y;
    int n0 = blockIdx.x * 64;
    int tid = threadIdx.x;
    int tx = tid & 7, ty = tid >> 3;

    unsigned long long acc2[8][4];
    #pragma unroll
    for (int i = 0; i < 8; i++)
        #pragma unroll
        for (int j = 0; j < 4; j++) acc2[i][j] = 0ULL;

    const float* fbase = feat + (size_t)b*Cc*Nn;

    for (int k0 = 0; k0 < Cc; k0 += 32) {
        const float4* ws = (const float4*)(g_w1t + (size_t)k0*Cc);
        float4* wd = (float4*)SM;
        #pragma unroll
        for (int i = 0; i < 8; i++) wd[i*256 + tid] = ws[i*256 + tid];
        #pragma unroll
        for (int i = 0; i < 2; i++) {
            int f4i = i*256 + tid;
            int kk = f4i >> 4, c4 = f4i & 15;
            int nbase = n0 + c4*4;
            const float* src = fbase + (size_t)(k0+kk)*Nn + nbase;
            float4 v;
            if (nbase + 3 < Nn) v = *(const float4*)src;
            else {
                v.x = (nbase+0 < Nn) ? src[0] : 0.f;
                v.y = (nbase+1 < Nn) ? src[1] : 0.f;
                v.z = (nbase+2 < Nn) ? src[2] : 0.f;
                v.w = 0.f;
            }
            *(float4*)&Fs[kk][c4*4] = v;
        }
        __syncthreads();
        #pragma unroll
        for (int kk = 0; kk < 32; kk++) {
            float4 wa = *(const float4*)&SM[kk*256 + ty*8];
            float4 wb = *(const float4*)&SM[kk*256 + ty*8 + 4];
            float wv[8] = {wa.x,wa.y,wa.z,wa.w,wb.x,wb.y,wb.z,wb.w};
            unsigned long long wp[8];
            #pragma unroll
            for (int i = 0; i < 8; i++) PACK2(wp[i], wv[i], wv[i]);
            const unsigned long long* fp = (const unsigned long long*)&Fs[kk][tx*8];
            unsigned long long f0 = fp[0], f1 = fp[1], f2 = fp[2], f3 = fp[3];
            #pragma unroll
            for (int i = 0; i < 8; i++) {
                FMA_F32X2(acc2[i][0], wp[i], f0, acc2[i][0]);
                FMA_F32X2(acc2[i][1], wp[i], f1, acc2[i][1]);
                FMA_F32X2(acc2[i][2], wp[i], f2, acc2[i][2]);
                FMA_F32X2(acc2[i][3], wp[i], f3, acc2[i][3]);
            }
        }
        __syncthreads();
    }

    // epilogue: +b1, BN, ReLU, W2 partials (3 channels)
    float p[3][8];
    #pragma unroll
    for (int c = 0; c < 3; c++)
        #pragma unroll
        for (int j = 0; j < 8; j++) p[c][j] = 0.f;
    #pragma unroll
    for (int i = 0; i < 8; i++) {
        int o = ty*8 + i;
        float sc  = gg[o] / sqrtf(gv[o] + 1e-5f);
        float sh  = __fsub_rn(gbe[o], __fmul_rn(gm[o], sc));
        float bb  = b1[o];
        float w20 = w2[o], w21 = w2[Cc+o], w22 = w2[2*Cc+o];
        float av[8];
        #pragma unroll
        for (int jp = 0; jp < 4; jp++) UNPACK2(av[2*jp], av[2*jp+1], acc2[i][jp]);
        #pragma unroll
        for (int j = 0; j < 8; j++) {
            float t = __fadd_rn(av[j], bb);
            t = __fadd_rn(__fmul_rn(t, sc), sh);
            t = fmaxf(t, 0.f);
            p[0][j] = __fadd_rn(p[0][j], __fmul_rn(w20, t));
            p[1][j] = __fadd_rn(p[1][j], __fmul_rn(w21, t));
            p[2][j] = __fadd_rn(p[2][j], __fmul_rn(w22, t));
        }
    }
    #pragma unroll
    for (int c = 0; c < 3; c++)
        #pragma unroll
        for (int j = 0; j < 8; j++)
            SM[c*2048 + ty*64 + tx*8 + j] = p[c][j];
    __syncthreads();
    if (tid < 192) {
        int c = tid >> 6, pt = tid & 63;
        float s = 0.f;
        #pragma unroll
        for (int t = 0; t < 32; t++) s = __fadd_rn(s, SM[c*2048 + t*64 + pt]);
        s = __fadd_rn(s, b2[c]);
        int n = n0 + pt;
        if (n < Nn) {
            if (c < 2) out[O_OBJ + ((size_t)b*2 + c)*Nn + n] = s;
            else       out[O_GR  + (size_t)b*Nn + n] = s;
        }
    }
}

// ============================================================
// K2a: per-chunk mask counts (parallel)
// ============================================================
__device__ __forceinline__ bool mask_flag(const float* out, int b, int n) {
    float o0 = out[O_OBJ + ((size_t)b*2 + 0)*Nn + n];
    float o1 = out[O_OBJ + ((size_t)b*2 + 1)*Nn + n];
    float gr = out[O_GR  + (size_t)b*Nn + n];
    return (o1 > o0) && (gr > 0.1f);
}

__global__ void __launch_bounds__(1024) k_maskcnt(const float* __restrict__ out)
{
    int b = blockIdx.y, ch = blockIdx.x;
    int tid = threadIdx.x, lane = tid & 31, wid = tid >> 5;
    int n = ch*1024 + tid;
    bool flag = (n < Nn) ? mask_flag(out, b, n) : false;
    unsigned bal = __ballot_sync(0xffffffffu, flag);
    __shared__ int wcnt[32];
    if (lane == 0) wcnt[wid] = __popc(bal);
    __syncthreads();
    if (tid < 32) {
        int v = __reduce_add_sync(0xffffffffu, wcnt[tid]);
        if (tid == 0) g_ccnt[b][ch] = v;
    }
}

// ============================================================
// K2b: tiny scan of chunk counts
// ============================================================
__global__ void k_scan()
{
    int b = threadIdx.x;
    if (b < Bb) {
        int off = 0;
        #pragma unroll
        for (int c = 0; c < NCH; c++) { g_coff[b][c] = off; off += g_ccnt[b][c]; }
        g_count[b] = off;
    }
}

// ============================================================
// K2c: stable ordered scatter (parallel)
// ============================================================
__global__ void __launch_bounds__(1024) k_scatter(const float* __restrict__ xyz,
                                                  const float* __restrict__ out)
{
    int b = blockIdx.y, ch = blockIdx.x;
    int tid = threadIdx.x, lane = tid & 31, wid = tid >> 5;
    int n = ch*1024 + tid;
    bool flag = (n < Nn) ? mask_flag(out, b, n) : false;
    unsigned bal = __ballot_sync(0xffffffffu, flag);
    __shared__ int wcnt[32], wex[32];
    if (lane == 0) wcnt[wid] = __popc(bal);
    __syncthreads();
    if (tid < 32) {
        int v = wcnt[tid];
        int incl = v;
        #pragma unroll
        for (int off = 1; off < 32; off <<= 1) {
            int o = __shfl_up_sync(0xffffffffu, incl, off);
            if (lane >= off) incl += o;
        }
        wex[tid] = incl - v;
    }
    __syncthreads();
    if (flag) {
        int pos = g_coff[b][ch] + wex[wid] + __popc(bal & ((1u << lane) - 1u));
        g_cx[b][pos] = xyz[((size_t)b*Nn + n)*3 + 0];
        g_cy[b][pos] = xyz[((size_t)b*Nn + n)*3 + 1];
        g_cz[b][pos] = xyz[((size_t)b*Nn + n)*3 + 2];
        g_cidx[b][pos] = n;
    }
}

// ============================================================
// K3: farthest point sampling — ONE barrier per iteration
//     parity-double-buffered per-warp (val, idx, coords) slots
// ============================================================
__global__ void __launch_bounds__(1024, 1) k_fps(float* __restrict__ out)
{
    int b = blockIdx.x;
    int tid = threadIdx.x;
    int lane = tid & 31, wid = tid >> 5;
    int M = g_count[b];

    __shared__ unsigned s_v[2][32], s_c[2][32];
    __shared__ float s_x[2][32], s_y[2][32], s_z[2][32];

    if (M <= 0) {
        for (int s = tid; s < Ss; s += 1024) {
            g_inds[b][s] = 0;
            out[O_GIND + (size_t)b*Ss + s] = 0.f;
        }
        return;
    }

    float px[20], py[20], pz[20], pd[20];
    #pragma unroll
    for (int j = 0; j < 20; j++) {
        int c = tid + j*1024;
        if (c < M) {
            px[j] = g_cx[b][c]; py[j] = g_cy[b][c]; pz[j] = g_cz[b][c];
            pd[j] = 1e10f;
        }
    }

    // first sample = first masked index; all threads load its coords (broadcast LDG)
    float qx = g_cx[b][0], qy = g_cy[b][0], qz = g_cz[b][0];
    if (tid == 0) {
        int i0 = g_cidx[b][0];
        g_inds[b][0] = i0;
        out[O_GIND + (size_t)b*Ss] = (float)i0;
    }

    for (int it = 1; it < Ss; it++) {
        int p = it & 1;
        float bv = -1.f; unsigned bc = 0xFFFFFFFFu;
        float bx = 0.f, by = 0.f, bz = 0.f;
        #pragma unroll
        for (int j = 0; j < 20; j++) {
            int c = tid + j*1024;
            if (c >= M) break;
            float dx = __fsub_rn(px[j], qx);
            float dy = __fsub_rn(py[j], qy);
            float dz = __fsub_rn(pz[j], qz);
            float d  = __fadd_rn(__fadd_rn(__fmul_rn(dx,dx), __fmul_rn(dy,dy)), __fmul_rn(dz,dz));
            float nd = fminf(pd[j], d);
            pd[j] = nd;
            if (nd > bv) { bv = nd; bc = (unsigned)c; bx = px[j]; by = py[j]; bz = pz[j]; }
        }
        unsigned vb = (bv >= 0.f) ? __float_as_uint(bv) : 0u;  // d>=0 -> bits order-preserving
        unsigned wmax = __reduce_max_sync(0xffffffffu, vb);
        unsigned cand = (vb == wmax) ? bc : 0xFFFFFFFFu;
        unsigned wc   = __reduce_min_sync(0xffffffffu, cand);  // lowest idx on ties
        if (vb == wmax && bc == wc && bc != 0xFFFFFFFFu) {     // unique owner writes coords
            s_x[p][wid] = bx; s_y[p][wid] = by; s_z[p][wid] = bz;
        }
        if (lane == 0) { s_v[p][wid] = wmax; s_c[p][wid] = wc; }
        __syncthreads();
        // every warp redundantly reduces the 32 slots — no second barrier
        unsigned v2 = s_v[p][lane], c2 = s_c[p][lane];
        unsigned m2 = __reduce_max_sync(0xffffffffu, v2);
        unsigned cd = (v2 == m2) ? c2 : 0xFFFFFFFFu;
        unsigned widx = __reduce_min_sync(0xffffffffu, cd);    // winning compacted index
        unsigned sel = (v2 == m2 && c2 == widx) ? (unsigned)lane : 63u;
        unsigned ws  = __reduce_min_sync(0xffffffffu, sel);    // slot holding its coords
        qx = s_x[p][ws]; qy = s_y[p][ws]; qz = s_z[p][ws];
        if (tid == 0) {
            int oi = g_cidx[b][widx];
            g_inds[b][it] = oi;
            out[O_GIND + (size_t)b*Ss + it] = (float)oi;
        }
    }
}

// ============================================================
// K4: gathers (xyz, features, graspness at sampled indices)
// ============================================================
__global__ void __launch_bounds__(256) k_gather(const float* __restrict__ xyz,
                                                const float* __restrict__ feat,
                                                float* __restrict__ out)
{
    int b = blockIdx.y;
    int bx = blockIdx.x;
    int tid = threadIdx.x;
    if (bx < 64) {
        int base = bx*4096;
        #pragma unroll
        for (int i = 0; i < 16; i++) {
            int e = base + i*256 + tid;
            int c = e >> 10, s = e & 1023;
            int idx = g_inds[b][s];
            out[O_GFEAT + ((size_t)b*Cc + c)*Ss + s] = feat[((size_t)b*Cc + c)*Nn + idx];
        }
    } else {
        for (int s = tid; s < Ss; s += 256) {
            int idx = g_inds[b][s];
            out[O_GXYZ + ((size_t)b*Ss + s)*3 + 0] = xyz[((size_t)b*Nn + idx)*3 + 0];
            out[O_GXYZ + ((size_t)b*Ss + s)*3 + 1] = xyz[((size_t)b*Nn + idx)*3 + 1];
            out[O_GXYZ + ((size_t)b*Ss + s)*3 + 2] = xyz[((size_t)b*Nn + idx)*3 + 2];
            out[O_FP2  + (size_t)b*Ss + s] = out[O_GR + (size_t)b*Nn + idx];
        }
    }
}

// ============================================================
// K5: fused GEMM2 + BN + ReLU + c2 head + views + rot (f32x2 FMA)
// ============================================================
__global__ void __launch_bounds__(256) k_gemm2(
    const float* __restrict__ c1b, const float* __restrict__ bg,
    const float* __restrict__ bbe, const float* __restrict__ bm,
    const float* __restrict__ bv,  const float* __restrict__ c2w,
    const float* __restrict__ c2b, float* __restrict__ out)
{
    __shared__ float SM[32*256];
    __shared__ float Fs[32][64];
    __shared__ float s_tn[Vv*3];
    __shared__ float s_vp[64][3];
    int b  = blockIdx.y;
    int n0 = blockIdx.x * 64;
    int tid = threadIdx.x;
    int tx = tid & 7, ty = tid >> 3;

    for (int i = tid; i < Vv*3; i += 256) s_tn[i] = g_tn[i];

    const float* fbase = out + O_GFEAT + (size_t)b*Cc*Ss;
    unsigned long long acc2[8][4];
    #pragma unroll
    for (int i = 0; i < 8; i++)
        #pragma unroll
        for (int j = 0; j < 4; j++) acc2[i][j] = 0ULL;

    for (int k0 = 0; k0 < Cc; k0 += 32) {
        const float4* ws = (const float4*)(g_c1t + (size_t)k0*Cc);
        float4* wd = (float4*)SM;
        #pragma unroll
        for (int i = 0; i < 8; i++) wd[i*256 + tid] = ws[i*256 + tid];
        #pragma unroll
        for (int i = 0; i < 2; i++) {
            int f4i = i*256 + tid;
            int kk = f4i >> 4, c4 = f4i & 15;
            *(float4*)&Fs[kk][c4*4] = *(const float4*)(fbase + (size_t)(k0+kk)*Ss + n0 + c4*4);
        }
        __syncthreads();
        #pragma unroll
        for (int kk = 0; kk < 32; kk++) {
            float4 wa = *(const float4*)&SM[kk*256 + ty*8];
            float4 wb = *(const float4*)&SM[kk*256 + ty*8 + 4];
            float wv[8] = {wa.x,wa.y,wa.z,wa.w,wb.x,wb.y,wb.z,wb.w};
            unsigned long long wp[8];
            #pragma unroll
            for (int i = 0; i < 8; i++) PACK2(wp[i], wv[i], wv[i]);
            const unsigned long long* fp = (const unsigned long long*)&Fs[kk][tx*8];
            unsigned long long f0 = fp[0], f1 = fp[1], f2 = fp[2], f3 = fp[3];
            #pragma unroll
            for (int i = 0; i < 8; i++) {
                FMA_F32X2(acc2[i][0], wp[i], f0, acc2[i][0]);
                FMA_F32X2(acc2[i][1], wp[i], f1, acc2[i][1]);
                FMA_F32X2(acc2[i][2], wp[i], f2, acc2[i][2]);
                FMA_F32X2(acc2[i][3], wp[i], f3, acc2[i][3]);
            }
        }
        __syncthreads();
    }

    float p[3][8];
    #pragma unroll
    for (int c = 0; c < 3; c++)
        #pragma unroll
        for (int j = 0; j < 8; j++) p[c][j] = 0.f;
    #pragma unroll
    for (int i = 0; i < 8; i++) {
        int o = ty*8 + i;
        float sc  = bg[o] / sqrtf(bv[o] + 1e-5f);
        float sh  = __fsub_rn(bbe[o], __fmul_rn(bm[o], sc));
        float bb  = c1b[o];
        float w20 = c2w[o], w21 = c2w[Cc+o], w22 = c2w[2*Cc+o];
        float av[8];
        #pragma unroll
        for (int jp = 0; jp < 4; jp++) UNPACK2(av[2*jp], av[2*jp+1], acc2[i][jp]);
        #pragma unroll
        for (int j = 0; j < 8; j++) {
            float t = __fadd_rn(av[j], bb);
            t = __fadd_rn(__fmul_rn(t, sc), sh);
            t = fmaxf(t, 0.f);
            p[0][j] = __fadd_rn(p[0][j], __fmul_rn(w20, t));
            p[1][j] = __fadd_rn(p[1][j], __fmul_rn(w21, t));
            p[2][j] = __fadd_rn(p[2][j], __fmul_rn(w22, t));
        }
    }
    #pragma unroll
    for (int c = 0; c < 3; c++)
        #pragma unroll
        for (int j = 0; j < 8; j++)
            SM[c*2048 + ty*64 + tx*8 + j] = p[c][j];
    __syncthreads();
    if (tid < 192) {
        int c = tid >> 6, pt = tid & 63;
        float s = 0.f;
        #pragma unroll
        for (int t = 0; t < 32; t++) s = __fadd_rn(s, SM[c*2048 + t*64 + pt]);
        s = __fadd_rn(s, c2b[c]);
        s_vp[pt][c] = s;
    }
    __syncthreads();
    if (tid < 64) {
        int pt = tid;
        int s  = n0 + pt;
        float x = s_vp[pt][0], y = s_vp[pt][1], z = s_vp[pt][2];
        size_t vo = O_VP + ((size_t)b*Ss + s)*3;
        out[vo+0] = x; out[vo+1] = y; out[vo+2] = z;

        float nrm = sqrtf(__fadd_rn(__fadd_rn(__fmul_rn(x,x),__fmul_rn(y,y)),__fmul_rn(z,z)));
        float den = fmaxf(nrm, 1e-8f);
        float vnx = x/den, vny = y/den, vnz = z/den;

        float bestc = -1e30f; int besti = 0;
        for (int v = 0; v < Vv; v++) {
            float cv = __fadd_rn(__fadd_rn(__fmul_rn(vnx, s_tn[v*3+0]),
                                           __fmul_rn(vny, s_tn[v*3+1])),
                                 __fmul_rn(vnz, s_tn[v*3+2]));
            if (cv > bestc) { bestc = cv; besti = v; }
        }
        out[O_TVI + (size_t)b*Ss + s] = (float)besti;

        float ax0 = -x, ax1 = -y, ax2 = -z;
        float ay0 = y, ay1 = -x, ay2 = 0.f;
        float ssum = __fadd_rn(__fadd_rn(__fmul_rn(ay0,ay0),__fmul_rn(ay1,ay1)),__fmul_rn(ay2,ay2));
        if (ssum == 0.f) { ay0 = 0.f; ay1 = 1.f; ay2 = 0.f; }
        float nax = sqrtf(__fadd_rn(__fadd_rn(__fmul_rn(ax0,ax0),__fmul_rn(ax1,ax1)),__fmul_rn(ax2,ax2)));
        float nay = sqrtf(__fadd_rn(__fadd_rn(__fmul_rn(ay0,ay0),__fmul_rn(ay1,ay1)),__fmul_rn(ay2,ay2)));
        float nx0 = ax0/nax, nx1 = ax1/nax, nx2 = ax2/nax;
        float ny0 = ay0/nay, ny1 = ay1/nay, ny2 = ay2/nay;
        float nz0 = __fsub_rn(__fmul_rn(nx1,ny2), __fmul_rn(nx2,ny1));
        float nz1 = __fsub_rn(__fmul_rn(nx2,ny0), __fmul_rn(nx0,ny2));
        float nz2 = __fsub_rn(__fmul_rn(nx0,ny1), __fmul_rn(nx1,ny0));
        size_t ro = O_ROT + ((size_t)b*Ss + s)*9;
        out[ro+0] = nx0; out[ro+1] = ny0; out[ro+2] = nz0;
        out[ro+3] = nx1; out[ro+4] = ny1; out[ro+5] = nz1;
        out[ro+6] = nx2; out[ro+7] = ny2; out[ro+8] = nz2;
    }
}

// ============================================================
extern "C" void kernel_launch(void* const* d_in, const int* in_sizes, int n_in,
                              void* d_out, int out_size)
{
    const float* xyz  = (const float*)d_in[0];
    const float* feat = (const float*)d_in[1];
    const float* w1   = (const float*)d_in[2];
    const float* b1   = (const float*)d_in[3];
    const float* gg   = (const float*)d_in[4];
    const float* gbe  = (const float*)d_in[5];
    const float* gm   = (const float*)d_in[6];
    const float* gv   = (const float*)d_in[7];
    const float* w2   = (const float*)d_in[8];
    const float* b2   = (const float*)d_in[9];
    const float* c1w  = (const float*)d_in[10];
    const float* c1b  = (const float*)d_in[11];
    const float* bng  = (const float*)d_in[12];
    const float* bnb  = (const float*)d_in[13];
    const float* bnm  = (const float*)d_in[14];
    const float* bnv  = (const float*)d_in[15];
    const float* c2w  = (const float*)d_in[16];
    const float* c2b  = (const float*)d_in[17];
    float* out = (float*)d_out;

    k_templates<<<1, 512>>>();
    k_transpose<<<(Cc*Cc + 255)/256, 256>>>(w1, c1w);
    k_gemm1<<<dim3(313, 4), 256>>>(feat, b1, gg, gbe, gm, gv, w2, b2, out);
    k_maskcnt<<<dim3(NCH, 4), 1024>>>(out);
    k_scan<<<1, 32>>>();
    k_scatter<<<dim3(NCH, 4), 1024>>>(xyz, out);
    k_fps<<<4, 1024>>>(out);
    k_gather<<<dim3(65, 4), 256>>>(xyz, feat, out);
    k_gemm2<<<dim3(16, 4), 256>>>(c1b, bng, bnb, bnm, bnv, c2w, c2b, out);
}

// round 5
// speedup vs baseline: 1.4851x; 1.4851x over previous
#include <cuda_runtime.h>
#include <math.h>

#define Bb 4
#define Nn 20000
#define Cc 256
#define Ss 1024
#define Vv 300
#define NCH 20   // chunks of 1024 covering 20000

// ---- output layout (floats), flattened reference tuple order ----
#define O_OBJ   ((size_t)0)                       // [B,2,N]   160000
#define O_GR    (O_OBJ   + (size_t)Bb*2*Nn)       // [B,N]      80000
#define O_GXYZ  (O_GR    + (size_t)Bb*Nn)         // [B,S,3]    12288
#define O_GIND  (O_GXYZ  + (size_t)Bb*Ss*3)       // [B,S]       4096
#define O_GFEAT (O_GIND  + (size_t)Bb*Ss)         // [B,C,S]  1048576
#define O_FP2   (O_GFEAT + (size_t)Bb*Cc*Ss)      // [B,S]       4096
#define O_VP    (O_FP2   + (size_t)Bb*Ss)         // [B,S,3]    12288
#define O_TVI   (O_VP    + (size_t)Bb*Ss*3)       // [B,S]       4096
#define O_ROT   (O_TVI   + (size_t)Bb*Ss)         // [B,S,3,3]  36864

// ---- scratch (device globals; no allocation allowed) ----
__device__ float g_w1t[Cc*Cc];
__device__ float g_c1t[Cc*Cc];
__device__ float g_cx[Bb][Nn];
__device__ float g_cy[Bb][Nn];
__device__ float g_cz[Bb][Nn];
__device__ int   g_cidx[Bb][Nn];
__device__ int   g_count[Bb];
__device__ int   g_ccnt[Bb][NCH];
__device__ int   g_coff[Bb][NCH];
__device__ int   g_inds[Bb][Ss];
__device__ float g_tn[Vv*3];

// ============================================================
// K0: template views (double math mirroring numpy, then fp32 normalize)
// ============================================================
__global__ void k_templates() {
    int i = blockIdx.x*blockDim.x + threadIdx.x;
    if (i >= Vv) return;
    double phi = (sqrt(5.0) - 1.0) / 2.0;
    double z   = (2.0*(double)i + 1.0)/(double)Vv - 1.0;
    double r2  = 1.0 - z*z; if (r2 < 0.0) r2 = 0.0;
    double r   = sqrt(r2);
    double ang = ((2.0*3.141592653589793)*(double)i)*phi;
    float x = (float)(r*cos(ang));
    float y = (float)(r*sin(ang));
    float zf = (float)z;
    float nrm = sqrtf(__fadd_rn(__fadd_rn(__fmul_rn(x,x),__fmul_rn(y,y)),__fmul_rn(zf,zf)));
    float den = fmaxf(nrm, 1e-8f);
    g_tn[i*3+0] = x/den; g_tn[i*3+1] = y/den; g_tn[i*3+2] = zf/den;
}

// ============================================================
// K0b: transpose both 256x256 weight matrices
// ============================================================
__global__ void k_transpose(const float* __restrict__ w1, const float* __restrict__ c1) {
    int idx = blockIdx.x*blockDim.x + threadIdx.x;
    if (idx < Cc*Cc) {
        int o = idx >> 8, k = idx & 255;
        g_w1t[k*Cc + o] = w1[idx];
        g_c1t[k*Cc + o] = c1[idx];
    }
}

// ============================================================
// K1: fused GEMM1 (W1 x feat) + BN + ReLU + W2 head (R2-proven fmaf path)
// ============================================================
__global__ void __launch_bounds__(256) k_gemm1(
    const float* __restrict__ feat, const float* __restrict__ b1,
    const float* __restrict__ gg,   const float* __restrict__ gbe,
    const float* __restrict__ gm,   const float* __restrict__ gv,
    const float* __restrict__ w2,   const float* __restrict__ b2,
    float* __restrict__ out)
{
    __shared__ float SM[32*256];
    __shared__ float Fs[32][64];
    int b  = blockIdx.y;
    int n0 = blockIdx.x * 64;
    int tid = threadIdx.x;
    int tx = tid & 7, ty = tid >> 3;

    float acc[8][8];
    #pragma unroll
    for (int i = 0; i < 8; i++)
        #pragma unroll
        for (int j = 0; j < 8; j++) acc[i][j] = 0.f;

    const float* fbase = feat + (size_t)b*Cc*Nn;

    for (int k0 = 0; k0 < Cc; k0 += 32) {
        const float4* ws = (const float4*)(g_w1t + (size_t)k0*Cc);
        float4* wd = (float4*)SM;
        #pragma unroll
        for (int i = 0; i < 8; i++) wd[i*256 + tid] = ws[i*256 + tid];
        #pragma unroll
        for (int i = 0; i < 2; i++) {
            int f4i = i*256 + tid;
            int kk = f4i >> 4, c4 = f4i & 15;
            int nbase = n0 + c4*4;
            const float* src = fbase + (size_t)(k0+kk)*Nn + nbase;
            float4 v;
            if (nbase + 3 < Nn) v = *(const float4*)src;
            else {
                v.x = (nbase+0 < Nn) ? src[0] : 0.f;
                v.y = (nbase+1 < Nn) ? src[1] : 0.f;
                v.z = (nbase+2 < Nn) ? src[2] : 0.f;
                v.w = 0.f;
            }
            *(float4*)&Fs[kk][c4*4] = v;
        }
        __syncthreads();
        #pragma unroll
        for (int kk = 0; kk < 32; kk++) {
            float4 wa = *(const float4*)&SM[kk*256 + ty*8];
            float4 wb = *(const float4*)&SM[kk*256 + ty*8 + 4];
            float4 fa = *(const float4*)&Fs[kk][tx*8];
            float4 fc = *(const float4*)&Fs[kk][tx*8 + 4];
            float wv[8] = {wa.x,wa.y,wa.z,wa.w,wb.x,wb.y,wb.z,wb.w};
            float fv[8] = {fa.x,fa.y,fa.z,fa.w,fc.x,fc.y,fc.z,fc.w};
            #pragma unroll
            for (int i = 0; i < 8; i++)
                #pragma unroll
                for (int j = 0; j < 8; j++)
                    acc[i][j] = fmaf(wv[i], fv[j], acc[i][j]);
        }
        __syncthreads();
    }

    // epilogue: +b1, BN, ReLU, W2 partials (3 channels)
    float p[3][8];
    #pragma unroll
    for (int c = 0; c < 3; c++)
        #pragma unroll
        for (int j = 0; j < 8; j++) p[c][j] = 0.f;
    #pragma unroll
    for (int i = 0; i < 8; i++) {
        int o = ty*8 + i;
        float sc  = gg[o] / sqrtf(gv[o] + 1e-5f);
        float sh  = __fsub_rn(gbe[o], __fmul_rn(gm[o], sc));
        float bb  = b1[o];
        float w20 = w2[o], w21 = w2[Cc+o], w22 = w2[2*Cc+o];
        #pragma unroll
        for (int j = 0; j < 8; j++) {
            float t = __fadd_rn(acc[i][j], bb);
            t = __fadd_rn(__fmul_rn(t, sc), sh);
            t = fmaxf(t, 0.f);
            p[0][j] = __fadd_rn(p[0][j], __fmul_rn(w20, t));
            p[1][j] = __fadd_rn(p[1][j], __fmul_rn(w21, t));
            p[2][j] = __fadd_rn(p[2][j], __fmul_rn(w22, t));
        }
    }
    #pragma unroll
    for (int c = 0; c < 3; c++)
        #pragma unroll
        for (int j = 0; j < 8; j++)
            SM[c*2048 + ty*64 + tx*8 + j] = p[c][j];
    __syncthreads();
    if (tid < 192) {
        int c = tid >> 6, pt = tid & 63;
        float s = 0.f;
        #pragma unroll
        for (int t = 0; t < 32; t++) s = __fadd_rn(s, SM[c*2048 + t*64 + pt]);
        s = __fadd_rn(s, b2[c]);
        int n = n0 + pt;
        if (n < Nn) {
            if (c < 2) out[O_OBJ + ((size_t)b*2 + c)*Nn + n] = s;
            else       out[O_GR  + (size_t)b*Nn + n] = s;
        }
    }
}

// ============================================================
// K2a: per-chunk mask counts (parallel)  [proven 4.4us]
// ============================================================
__device__ __forceinline__ bool mask_flag(const float* out, int b, int n) {
    float o0 = out[O_OBJ + ((size_t)b*2 + 0)*Nn + n];
    float o1 = out[O_OBJ + ((size_t)b*2 + 1)*Nn + n];
    float gr = out[O_GR  + (size_t)b*Nn + n];
    return (o1 > o0) && (gr > 0.1f);
}

__global__ void __launch_bounds__(1024) k_maskcnt(const float* __restrict__ out)
{
    int b = blockIdx.y, ch = blockIdx.x;
    int tid = threadIdx.x, lane = tid & 31, wid = tid >> 5;
    int n = ch*1024 + tid;
    bool flag = (n < Nn) ? mask_flag(out, b, n) : false;
    unsigned bal = __ballot_sync(0xffffffffu, flag);
    __shared__ int wcnt[32];
    if (lane == 0) wcnt[wid] = __popc(bal);
    __syncthreads();
    if (tid < 32) {
        int v = __reduce_add_sync(0xffffffffu, wcnt[tid]);
        if (tid == 0) g_ccnt[b][ch] = v;
    }
}

// ============================================================
// K2b: tiny scan of chunk counts
// ============================================================
__global__ void k_scan()
{
    int b = threadIdx.x;
    if (b < Bb) {
        int off = 0;
        #pragma unroll
        for (int c = 0; c < NCH; c++) { g_coff[b][c] = off; off += g_ccnt[b][c]; }
        g_count[b] = off;
    }
}

// ============================================================
// K2c: stable ordered scatter (parallel)
// ============================================================
__global__ void __launch_bounds__(1024) k_scatter(const float* __restrict__ xyz,
                                                  const float* __restrict__ out)
{
    int b = blockIdx.y, ch = blockIdx.x;
    int tid = threadIdx.x, lane = tid & 31, wid = tid >> 5;
    int n = ch*1024 + tid;
    bool flag = (n < Nn) ? mask_flag(out, b, n) : false;
    unsigned bal = __ballot_sync(0xffffffffu, flag);
    __shared__ int wcnt[32], wex[32];
    if (lane == 0) wcnt[wid] = __popc(bal);
    __syncthreads();
    if (tid < 32) {
        int v = wcnt[tid];
        int incl = v;
        #pragma unroll
        for (int off = 1; off < 32; off <<= 1) {
            int o = __shfl_up_sync(0xffffffffu, incl, off);
            if (lane >= off) incl += o;
        }
        wex[tid] = incl - v;
    }
    __syncthreads();
    if (flag) {
        int pos = g_coff[b][ch] + wex[wid] + __popc(bal & ((1u << lane) - 1u));
        g_cx[b][pos] = xyz[((size_t)b*Nn + n)*3 + 0];
        g_cy[b][pos] = xyz[((size_t)b*Nn + n)*3 + 1];
        g_cz[b][pos] = xyz[((size_t)b*Nn + n)*3 + 2];
        g_cidx[b][pos] = n;
    }
}

// ============================================================
// K3: farthest point sampling (R2-proven two-barrier version)
// ============================================================
__global__ void __launch_bounds__(1024, 1) k_fps(float* __restrict__ out)
{
    int b = blockIdx.x;
    int tid = threadIdx.x;
    int lane = tid & 31, wid = tid >> 5;
    int M = g_count[b];
    __shared__ float s_q[3];
    __shared__ unsigned s_v[32], s_c[32];

    if (M <= 0) {
        for (int s = tid; s < Ss; s += 1024) {
            g_inds[b][s] = 0;
            out[O_GIND + (size_t)b*Ss + s] = 0.f;
        }
        return;
    }

    float px[20], py[20], pz[20], pd[20];
    #pragma unroll
    for (int j = 0; j < 20; j++) {
        int c = tid + j*1024;
        if (c < M) {
            px[j] = g_cx[b][c]; py[j] = g_cy[b][c]; pz[j] = g_cz[b][c];
            pd[j] = 1e10f;
        }
    }

    if (tid == 0) {
        int i0 = g_cidx[b][0];                       // first = argmax(mask) = first masked index
        g_inds[b][0] = i0;
        out[O_GIND + (size_t)b*Ss] = (float)i0;
        s_q[0] = g_cx[b][0]; s_q[1] = g_cy[b][0]; s_q[2] = g_cz[b][0];
    }
    __syncthreads();

    for (int it = 1; it < Ss; it++) {
        float qx = s_q[0], qy = s_q[1], qz = s_q[2];
        float bv = -1.f; unsigned bc = 0xFFFFFFFFu;
        #pragma unroll
        for (int j = 0; j < 20; j++) {
            int c = tid + j*1024;
            if (c >= M) break;
            float dx = __fsub_rn(px[j], qx);
            float dy = __fsub_rn(py[j], qy);
            float dz = __fsub_rn(pz[j], qz);
            float d  = __fadd_rn(__fadd_rn(__fmul_rn(dx,dx), __fmul_rn(dy,dy)), __fmul_rn(dz,dz));
            float nd = fminf(pd[j], d);
            pd[j] = nd;
            if (nd > bv) { bv = nd; bc = (unsigned)c; }   // strict > keeps lowest index on ties
        }
        unsigned vb = (bv >= 0.f) ? __float_as_uint(bv) : 0u;   // dists >= 0 -> bits order-preserving
        unsigned wmax = __reduce_max_sync(0xffffffffu, vb);
        unsigned cand = (vb == wmax) ? bc : 0xFFFFFFFFu;
        unsigned wc   = __reduce_min_sync(0xffffffffu, cand);
        if (lane == 0) { s_v[wid] = wmax; s_c[wid] = wc; }
        __syncthreads();
        if (wid == 0) {
            unsigned v2 = s_v[lane], c2 = s_c[lane];
            unsigned m2 = __reduce_max_sync(0xffffffffu, v2);
            unsigned cd = (v2 == m2) ? c2 : 0xFFFFFFFFu;
            unsigned cw = __reduce_min_sync(0xffffffffu, cd);
            if (lane == 0) {
                int oi = g_cidx[b][cw];
                g_inds[b][it] = oi;
                out[O_GIND + (size_t)b*Ss + it] = (float)oi;
                s_q[0] = g_cx[b][cw]; s_q[1] = g_cy[b][cw]; s_q[2] = g_cz[b][cw];
            }
        }
        __syncthreads();
    }
}

// ============================================================
// K4: gathers (xyz, features, graspness at sampled indices)
// ============================================================
__global__ void __launch_bounds__(256) k_gather(const float* __restrict__ xyz,
                                                const float* __restrict__ feat,
                                                float* __restrict__ out)
{
    int b = blockIdx.y;
    int bx = blockIdx.x;
    int tid = threadIdx.x;
    if (bx < 64) {
        int base = bx*4096;
        #pragma unroll
        for (int i = 0; i < 16; i++) {
            int e = base + i*256 + tid;
            int c = e >> 10, s = e & 1023;
            int idx = g_inds[b][s];
            out[O_GFEAT + ((size_t)b*Cc + c)*Ss + s] = feat[((size_t)b*Cc + c)*Nn + idx];
        }
    } else {
        for (int s = tid; s < Ss; s += 256) {
            int idx = g_inds[b][s];
            out[O_GXYZ + ((size_t)b*Ss + s)*3 + 0] = xyz[((size_t)b*Nn + idx)*3 + 0];
            out[O_GXYZ + ((size_t)b*Ss + s)*3 + 1] = xyz[((size_t)b*Nn + idx)*3 + 1];
            out[O_GXYZ + ((size_t)b*Ss + s)*3 + 2] = xyz[((size_t)b*Nn + idx)*3 + 2];
            out[O_FP2  + (size_t)b*Ss + s] = out[O_GR + (size_t)b*Nn + idx];
        }
    }
}

// ============================================================
// K5: fused GEMM2 + BN + ReLU + c2 head + views + rot (R2-proven)
// ============================================================
__global__ void __launch_bounds__(256) k_gemm2(
    const float* __restrict__ c1b, const float* __restrict__ bg,
    const float* __restrict__ bbe, const float* __restrict__ bm,
    const float* __restrict__ bv,  const float* __restrict__ c2w,
    const float* __restrict__ c2b, float* __restrict__ out)
{
    __shared__ float SM[32*256];
    __shared__ float Fs[32][64];
    __shared__ float s_tn[Vv*3];
    __shared__ float s_vp[64][3];
    int b  = blockIdx.y;
    int n0 = blockIdx.x * 64;
    int tid = threadIdx.x;
    int tx = tid & 7, ty = tid >> 3;

    for (int i = tid; i < Vv*3; i += 256) s_tn[i] = g_tn[i];

    const float* fbase = out + O_GFEAT + (size_t)b*Cc*Ss;
    float acc[8][8];
    #pragma unroll
    for (int i = 0; i < 8; i++)
        #pragma unroll
        for (int j = 0; j < 8; j++) acc[i][j] = 0.f;

    for (int k0 = 0; k0 < Cc; k0 += 32) {
        const float4* ws = (const float4*)(g_c1t + (size_t)k0*Cc);
        float4* wd = (float4*)SM;
        #pragma unroll
        for (int i = 0; i < 8; i++) wd[i*256 + tid] = ws[i*256 + tid];
        #pragma unroll
        for (int i = 0; i < 2; i++) {
            int f4i = i*256 + tid;
            int kk = f4i >> 4, c4 = f4i & 15;
            *(float4*)&Fs[kk][c4*4] = *(const float4*)(fbase + (size_t)(k0+kk)*Ss + n0 + c4*4);
        }
        __syncthreads();
        #pragma unroll
        for (int kk = 0; kk < 32; kk++) {
            float4 wa = *(const float4*)&SM[kk*256 + ty*8];
            float4 wb = *(const float4*)&SM[kk*256 + ty*8 + 4];
            float4 fa = *(const float4*)&Fs[kk][tx*8];
            float4 fc = *(const float4*)&Fs[kk][tx*8 + 4];
            float wv[8] = {wa.x,wa.y,wa.z,wa.w,wb.x,wb.y,wb.z,wb.w};
            float fv[8] = {fa.x,fa.y,fa.z,fa.w,fc.x,fc.y,fc.z,fc.w};
            #pragma unroll
            for (int i = 0; i < 8; i++)
                #pragma unroll
                for (int j = 0; j < 8; j++)
                    acc[i][j] = fmaf(wv[i], fv[j], acc[i][j]);
        }
        __syncthreads();
    }

    float p[3][8];
    #pragma unroll
    for (int c = 0; c < 3; c++)
        #pragma unroll
        for (int j = 0; j < 8; j++) p[c][j] = 0.f;
    #pragma unroll
    for (int i = 0; i < 8; i++) {
        int o = ty*8 + i;
        float sc  = bg[o] / sqrtf(bv[o] + 1e-5f);
        float sh  = __fsub_rn(bbe[o], __fmul_rn(bm[o], sc));
        float bb  = c1b[o];
        float w20 = c2w[o], w21 = c2w[Cc+o], w22 = c2w[2*Cc+o];
        #pragma unroll
        for (int j = 0; j < 8; j++) {
            float t = __fadd_rn(acc[i][j], bb);
            t = __fadd_rn(__fmul_rn(t, sc), sh);
            t = fmaxf(t, 0.f);
            p[0][j] = __fadd_rn(p[0][j], __fmul_rn(w20, t));
            p[1][j] = __fadd_rn(p[1][j], __fmul_rn(w21, t));
            p[2][j] = __fadd_rn(p[2][j], __fmul_rn(w22, t));
        }
    }
    #pragma unroll
    for (int c = 0; c < 3; c++)
        #pragma unroll
        for (int j = 0; j < 8; j++)
            SM[c*2048 + ty*64 + tx*8 + j] = p[c][j];
    __syncthreads();
    if (tid < 192) {
        int c = tid >> 6, pt = tid & 63;
        float s = 0.f;
        #pragma unroll
        for (int t = 0; t < 32; t++) s = __fadd_rn(s, SM[c*2048 + t*64 + pt]);
        s = __fadd_rn(s, c2b[c]);
        s_vp[pt][c] = s;
    }
    __syncthreads();
    if (tid < 64) {
        int pt = tid;
        int s  = n0 + pt;
        float x = s_vp[pt][0], y = s_vp[pt][1], z = s_vp[pt][2];
        size_t vo = O_VP + ((size_t)b*Ss + s)*3;
        out[vo+0] = x; out[vo+1] = y; out[vo+2] = z;

        float nrm = sqrtf(__fadd_rn(__fadd_rn(__fmul_rn(x,x),__fmul_rn(y,y)),__fmul_rn(z,z)));
        float den = fmaxf(nrm, 1e-8f);
        float vnx = x/den, vny = y/den, vnz = z/den;

        float bestc = -1e30f; int besti = 0;
        for (int v = 0; v < Vv; v++) {
            float cv = __fadd_rn(__fadd_rn(__fmul_rn(vnx, s_tn[v*3+0]),
                                           __fmul_rn(vny, s_tn[v*3+1])),
                                 __fmul_rn(vnz, s_tn[v*3+2]));
            if (cv > bestc) { bestc = cv; besti = v; }
        }
        out[O_TVI + (size_t)b*Ss + s] = (float)besti;

        // rotation matrix from towards = -vp
        float ax0 = -x, ax1 = -y, ax2 = -z;
        float ay0 = y, ay1 = -x, ay2 = 0.f;     // (-ax1, ax0, 0)
        float ssum = __fadd_rn(__fadd_rn(__fmul_rn(ay0,ay0),__fmul_rn(ay1,ay1)),__fmul_rn(ay2,ay2));
        if (ssum == 0.f) { ay0 = 0.f; ay1 = 1.f; ay2 = 0.f; }
        float nax = sqrtf(__fadd_rn(__fadd_rn(__fmul_rn(ax0,ax0),__fmul_rn(ax1,ax1)),__fmul_rn(ax2,ax2)));
        float nay = sqrtf(__fadd_rn(__fadd_rn(__fmul_rn(ay0,ay0),__fmul_rn(ay1,ay1)),__fmul_rn(ay2,ay2)));
        float nx0 = ax0/nax, nx1 = ax1/nax, nx2 = ax2/nax;
        float ny0 = ay0/nay, ny1 = ay1/nay, ny2 = ay2/nay;
        float nz0 = __fsub_rn(__fmul_rn(nx1,ny2), __fmul_rn(nx2,ny1));
        float nz1 = __fsub_rn(__fmul_rn(nx2,ny0), __fmul_rn(nx0,ny2));
        float nz2 = __fsub_rn(__fmul_rn(nx0,ny1), __fmul_rn(nx1,ny0));
        size_t ro = O_ROT + ((size_t)b*Ss + s)*9;
        out[ro+0] = nx0; out[ro+1] = ny0; out[ro+2] = nz0;
        out[ro+3] = nx1; out[ro+4] = ny1; out[ro+5] = nz1;
        out[ro+6] = nx2; out[ro+7] = ny2; out[ro+8] = nz2;
    }
}

// ============================================================
extern "C" void kernel_launch(void* const* d_in, const int* in_sizes, int n_in,
                              void* d_out, int out_size)
{
    const float* xyz  = (const float*)d_in[0];
    const float* feat = (const float*)d_in[1];
    const float* w1   = (const float*)d_in[2];
    const float* b1   = (const float*)d_in[3];
    const float* gg   = (const float*)d_in[4];
    const float* gbe  = (const float*)d_in[5];
    const float* gm   = (const float*)d_in[6];
    const float* gv   = (const float*)d_in[7];
    const float* w2   = (const float*)d_in[8];
    const float* b2   = (const float*)d_in[9];
    const float* c1w  = (const float*)d_in[10];
    const float* c1b  = (const float*)d_in[11];
    const float* bng  = (const float*)d_in[12];
    const float* bnb  = (const float*)d_in[13];
    const float* bnm  = (const float*)d_in[14];
    const float* bnv  = (const float*)d_in[15];
    const float* c2w  = (const float*)d_in[16];
    const float* c2b  = (const float*)d_in[17];
    float* out = (float*)d_out;

    k_templates<<<1, 512>>>();
    k_transpose<<<(Cc*Cc + 255)/256, 256>>>(w1, c1w);
    k_gemm1<<<dim3(313, 4), 256>>>(feat, b1, gg, gbe, gm, gv, w2, b2, out);
    k_maskcnt<<<dim3(NCH, 4), 1024>>>(out);
    k_scan<<<1, 32>>>();
    k_scatter<<<dim3(NCH, 4), 1024>>>(xyz, out);
    k_fps<<<4, 1024>>>(out);
    k_gather<<<dim3(65, 4), 256>>>(xyz, feat, out);
    k_gemm2<<<dim3(16, 4), 256>>>(c1b, bng, bnb, bnm, bnv, c2w, c2b, out);
}